// round 13
// baseline (speedup 1.0000x reference)
#include <cuda_runtime.h>
#include <math.h>
#include <stdint.h>
#include <mma.h>

using namespace nvcuda;

// Problem constants
#define NTOT 50000
#define EDIM 1000
#define DM   256
#define HEADS 4
#define MF   30
#define LNUM 3
#define NF   (HEADS * MF)          // 120 feature columns
#define NQK  (2 * NF)              // 240: [Qp | Kp] merged

// ---------------------------------------------------------------------------
// Scratch (device globals — no allocations allowed)
// ---------------------------------------------------------------------------
__device__ float g_z  [NTOT * DM];
__device__ float g_V  [NTOT * HEADS * DM];
__device__ float g_Zb [NTOT * HEADS * DM];
__device__ float g_QKp[NTOT * NQK];
__device__ float g_KV [HEADS * MF * DM];
__device__ float g_Ks [HEADS * MF];
// transposed / folded weights
__device__ float g_WT[2079440];

#define WT_IN   0
#define WT_HE   65536
#define WT_V(l) (321536  + (l) * 262144)
#define WT_O(l) (1107968 + (l) * 262144)
#define WQK(l)  (1894400 + (l) * 61440)     // 240 rows x 256 (rows 0-119 Q, 120-239 K)
#define BQK(l)  (2078720 + (l) * 240)

// ---------------------------------------------------------------------------
// cp.async helpers (base ISA, sm_80+)
// ---------------------------------------------------------------------------
__device__ __forceinline__ uint32_t smem_u32(const void* p) {
    uint32_t a;
    asm("{ .reg .u64 t; cvta.to.shared.u64 t, %1; cvt.u32.u64 %0, t; }"
        : "=r"(a) : "l"(p));
    return a;
}

__device__ __forceinline__ void cpasync16(uint32_t dst, const void* src, int srcsize) {
    asm volatile("cp.async.cg.shared.global [%0], [%1], 16, %2;"
        :: "r"(dst), "l"(src), "r"(srcsize) : "memory");
}
#define CP_COMMIT() asm volatile("cp.async.commit_group;" ::: "memory")
#define CP_WAIT1()  asm volatile("cp.async.wait_group 1;" ::: "memory")

// ---------------------------------------------------------------------------
// WMMA TF32 GEMM: C[M x Nn] = A[M x K] @ Bt^T (+bias) (+C) (or exp epilogue)
//   A  : [M, K]  row-major fp32
//   Bt : [Nn, K] row-major fp32 (K-major == wmma col_major B)
//   Block tile 128 x 256, BK = 32, 8 warps (warp tile 64 x 64). K % 4 == 0.
//   mode: 0 = C = v + bias ; 1 = C += v + bias ; 2 = C = exp(v + bias) + 1e-6
// ---------------------------------------------------------------------------
#define BK 32
#define ROWF 36
#define STAGE_F ((128 + 256) * ROWF)     // 13824 floats = 55296 B per stage
#define CS_PITCH 260
#define GEMM_SMEM (128 * CS_PITCH * 4)   // 133120 B (epilogue staging dominates)

__global__ __launch_bounds__(256, 1)
void gemm_tc(const float* __restrict__ A, const float* __restrict__ Bt,
             float* __restrict__ C, const float* __restrict__ bias,
             int M, int Nn, int K, int Cstride, int mode)
{
    extern __shared__ __align__(16) float smem[];

    const int tid  = threadIdx.x;
    const int wid  = tid >> 5;
    const int wm   = wid & 1;          // 0..1 -> 64-row slab
    const int wn   = wid >> 1;         // 0..3 -> 64-col slab
    const int row0 = blockIdx.y * 128;
    const int col0 = blockIdx.x * 256;

    const int T = (K + BK - 1) / BK;

    wmma::fragment<wmma::accumulator, 16, 16, 8, float> acc[4][4];
#pragma unroll
    for (int i = 0; i < 4; i++)
#pragma unroll
        for (int j = 0; j < 4; j++) wmma::fill_fragment(acc[i][j], 0.f);

    auto load_tile = [&](int tt, int ss) {
        float* As = smem + ss * STAGE_F;
        float* Bs = As + 128 * ROWF;
        const uint32_t asb = smem_u32(As);
        const uint32_t bsb = smem_u32(Bs);
        const int kbase = tt * BK;
#pragma unroll
        for (int i = 0; i < 4; i++) {          // A: 1024 16B chunks
            const int id  = tid + i * 256;
            const int row = id >> 3, c = id & 7;
            const int gr = row0 + row;
            const int gk = kbase + c * 4;
            const int ok = (gr < M) && (gk + 4 <= K);
            const float* src = ok ? (A + (size_t)gr * K + gk) : A;
            cpasync16(asb + (row * ROWF + c * 4) * 4, src, ok ? 16 : 0);
        }
#pragma unroll
        for (int i = 0; i < 8; i++) {          // B: 2048 16B chunks
            const int id  = tid + i * 256;
            const int row = id >> 3, c = id & 7;
            const int gn = col0 + row;
            const int gk = kbase + c * 4;
            const int ok = (gn < Nn) && (gk + 4 <= K);
            const float* src = ok ? (Bt + (size_t)gn * K + gk) : Bt;
            cpasync16(bsb + (row * ROWF + c * 4) * 4, src, ok ? 16 : 0);
        }
    };

    load_tile(0, 0);
    CP_COMMIT();

    for (int t = 0; t < T; t++) {
        if (t + 1 < T) load_tile(t + 1, (t + 1) & 1);
        CP_COMMIT();
        CP_WAIT1();
        __syncthreads();

        const float* As = smem + (t & 1) * STAGE_F;
        const float* Bs = As + 128 * ROWF;

#pragma unroll
        for (int ks = 0; ks < 4; ks++) {
            const int k0 = ks * 8;
            wmma::fragment<wmma::matrix_a, 16, 16, 8, wmma::precision::tf32,
                           wmma::row_major> af[4];
            wmma::fragment<wmma::matrix_b, 16, 16, 8, wmma::precision::tf32,
                           wmma::col_major> bf[4];
#pragma unroll
            for (int i = 0; i < 4; i++) {
                wmma::load_matrix_sync(af[i], As + (wm * 64 + i * 16) * ROWF + k0, ROWF);
#pragma unroll
                for (int e = 0; e < af[i].num_elements; e++)
                    af[i].x[e] = wmma::__float_to_tf32(af[i].x[e]);
            }
#pragma unroll
            for (int j = 0; j < 4; j++) {
                wmma::load_matrix_sync(bf[j], Bs + (wn * 64 + j * 16) * ROWF + k0, ROWF);
#pragma unroll
                for (int e = 0; e < bf[j].num_elements; e++)
                    bf[j].x[e] = wmma::__float_to_tf32(bf[j].x[e]);
            }
#pragma unroll
            for (int i = 0; i < 4; i++)
#pragma unroll
                for (int j = 0; j < 4; j++)
                    wmma::mma_sync(acc[i][j], af[i], bf[j], acc[i][j]);
        }
        __syncthreads();
    }

    // epilogue via smem staging (128 x 260)
    float* Cs = smem;
#pragma unroll
    for (int i = 0; i < 4; i++)
#pragma unroll
        for (int j = 0; j < 4; j++)
            wmma::store_matrix_sync(Cs + (wm * 64 + i * 16) * CS_PITCH + wn * 64 + j * 16,
                                    acc[i][j], CS_PITCH, wmma::mem_row_major);
    __syncthreads();

    const int r    = tid >> 1;         // 0..127
    const int half = tid & 1;          // 0..1 -> 128-col half
    const int gr   = row0 + r;
    if (gr < M) {
        const float* sp = Cs + r * CS_PITCH + half * 128;
#pragma unroll
        for (int j = 0; j < 32; j++) {
            const int cc = col0 + half * 128 + j * 4;
            if (cc + 4 > Nn) break;
            float4 v = *(const float4*)(sp + j * 4);
            float4 bv = *(const float4*)(bias + cc);
            v.x += bv.x; v.y += bv.y; v.z += bv.z; v.w += bv.w;
            float* cp = C + (size_t)gr * Cstride + cc;
            if (mode == 1) {
                float4 o = *(float4*)cp;
                v.x += o.x; v.y += o.y; v.z += o.z; v.w += o.w;
            } else if (mode == 2) {
                v.x = __expf(v.x) + 1e-6f; v.y = __expf(v.y) + 1e-6f;
                v.z = __expf(v.z) + 1e-6f; v.w = __expf(v.w) + 1e-6f;
            }
            *(float4*)cp = v;
        }
    }
}

// ---------------------------------------------------------------------------
// Mega-transpose: all weight transposes in ONE launch.
//   z: 0=W_in(256,256) 1=W_he(1000,256) 2..4=Wv[l](256,1024) 5..7=Wo[l](1024,256)
// ---------------------------------------------------------------------------
__global__ void mega_transpose(const float* __restrict__ W_in,
                               const float* __restrict__ W_he,
                               const float* __restrict__ Wv,
                               const float* __restrict__ Wo,
                               float* __restrict__ WT)
{
    const int z = blockIdx.z;
    const float* src; float* dst; int K, Nn;
    if (z == 0)      { src = W_in; dst = WT + WT_IN; K = 256;  Nn = 256; }
    else if (z == 1) { src = W_he; dst = WT + WT_HE; K = EDIM; Nn = 256; }
    else if (z < 5)  { const int l = z - 2;
                       src = Wv + (size_t)l * DM * HEADS * DM;
                       dst = WT + WT_V(l); K = 256; Nn = 1024; }
    else             { const int l = z - 5;
                       src = Wo + (size_t)l * DM * HEADS * DM;
                       dst = WT + WT_O(l); K = 1024; Nn = 256; }

    const int k0 = blockIdx.x * 32, n0 = blockIdx.y * 32;
    if (k0 >= K || n0 >= Nn) return;

    __shared__ float tile[32][33];
    const int tx = threadIdx.x, ty = threadIdx.y;
#pragma unroll
    for (int r = 0; r < 4; r++) {
        const int k = k0 + ty + r * 8;
        if (k < K && n0 + tx < Nn) tile[ty + r * 8][tx] = src[(size_t)k * Nn + n0 + tx];
    }
    __syncthreads();
#pragma unroll
    for (int r = 0; r < 4; r++) {
        const int n = n0 + ty + r * 8;
        if (n < Nn && k0 + tx < K) dst[(size_t)n * K + k0 + tx] = tile[tx][ty + r * 8];
    }
}

// ---------------------------------------------------------------------------
// Mega-fold: all FAVOR+ weight folds in ONE launch.
//   grid (NF, 2, LNUM); y=0 -> Q, y=1 -> K
//   Wout[h*MF+m, k] = c * sum_d W[k, h*256+d] * proj[m, d]
// ---------------------------------------------------------------------------
__global__ __launch_bounds__(256)
void mega_fold(const float* __restrict__ Wq, const float* __restrict__ bq,
               const float* __restrict__ Wk, const float* __restrict__ bk,
               const float* __restrict__ proj, float* __restrict__ WT)
{
    __shared__ float ps[DM];
    const int l   = blockIdx.z;
    const int isK = blockIdx.y;
    const float* W = (isK ? Wk : Wq) + (size_t)l * DM * HEADS * DM;
    const float* b = (isK ? bk : bq) + (size_t)l * (HEADS * DM);
    float* Wout = WT + WQK(l) + isK * (NF * DM);
    float* bout = WT + BQK(l) + isK * NF;

    const int nn = blockIdx.x;       // 0..119
    const int h = nn / MF, m = nn % MF;
    const int k = threadIdx.x;       // 0..255
    const float c = 0.25f * 0.18257418583505536f;
    ps[k] = c * proj[(size_t)m * DM + k];
    __syncthreads();

    float s = 0.f;
    const float* wp = W + (size_t)k * (HEADS * DM) + h * DM;
#pragma unroll 8
    for (int d = 0; d < DM; d++) s = fmaf(wp[d], ps[d], s);
    Wout[(size_t)nn * DM + k] = s;

    if (k == 0) {
        float sb = 0.f;
        const float* bp = b + h * DM;
        for (int d = 0; d < DM; d++) sb = fmaf(bp[d], ps[d], sb);
        bout[nn] = sb;
    }
}

// ---------------------------------------------------------------------------
// LayerNorm + ELU
// ---------------------------------------------------------------------------
__global__ void ln_elu_kernel(const float* __restrict__ h,
                              const float* __restrict__ gamma,
                              const float* __restrict__ beta,
                              float* __restrict__ z)
{
    const int gw   = blockIdx.x * (blockDim.x >> 5) + (threadIdx.x >> 5);
    const int lane = threadIdx.x & 31;
    if (gw >= NTOT) return;

    const float4* hp = (const float4*)(h + (size_t)gw * DM);
    float4 v0 = hp[lane * 2];
    float4 v1 = hp[lane * 2 + 1];
    float vv[8] = {v0.x, v0.y, v0.z, v0.w, v1.x, v1.y, v1.z, v1.w};

    float s = 0.f;
#pragma unroll
    for (int i = 0; i < 8; i++) s += vv[i];
#pragma unroll
    for (int o = 16; o; o >>= 1) s += __shfl_xor_sync(0xffffffffu, s, o);
    const float mean = s * (1.0f / DM);

    float sq = 0.f;
#pragma unroll
    for (int i = 0; i < 8; i++) { float d = vv[i] - mean; sq = fmaf(d, d, sq); }
#pragma unroll
    for (int o = 16; o; o >>= 1) sq += __shfl_xor_sync(0xffffffffu, sq, o);
    const float inv = rsqrtf(sq * (1.0f / DM) + 1e-5f);

    const int c = lane * 8;
    float out[8];
#pragma unroll
    for (int i = 0; i < 8; i++) {
        float t = (vv[i] - mean) * inv * gamma[c + i] + beta[c + i];
        out[i] = (t > 0.f) ? t : expm1f(t);
    }
    float4* zp = (float4*)(z + (size_t)gw * DM);
    zp[lane * 2]     = make_float4(out[0], out[1], out[2], out[3]);
    zp[lane * 2 + 1] = make_float4(out[4], out[5], out[6], out[7]);
}

// ---------------------------------------------------------------------------
// Zero KV / Ksum
// ---------------------------------------------------------------------------
__global__ void zero_kv_kernel()
{
    const int i = blockIdx.x * blockDim.x + threadIdx.x;
    if (i < HEADS * MF * DM) g_KV[i] = 0.f;
    if (i < HEADS * MF)      g_Ks[i] = 0.f;
}

// ---------------------------------------------------------------------------
// KV = sum_n Kp ⊗ V ; Ksum = sum_n Kp   (Kp = QKp + 120, row stride 240)
// ---------------------------------------------------------------------------
__global__ __launch_bounds__(256)
void kv_kernel(const float* __restrict__ Kp, const float* __restrict__ V)
{
    __shared__ float kpS[128][31];
    const int h   = blockIdx.y;
    const int n0  = blockIdx.x * 128;
    const int tid = threadIdx.x;
    const int rows = min(128, NTOT - n0);

    for (int i = tid; i < rows * MF; i += 256) {
        const int r = i / MF, m = i % MF;
        kpS[r][m] = Kp[(size_t)(n0 + r) * NQK + h * MF + m];
    }
    __syncthreads();

    float acc[MF];
#pragma unroll
    for (int m = 0; m < MF; m++) acc[m] = 0.f;

    for (int r = 0; r < rows; r++) {
        const float v = V[((size_t)(n0 + r) * HEADS + h) * DM + tid];
#pragma unroll
        for (int m = 0; m < MF; m++)
            acc[m] = fmaf(kpS[r][m], v, acc[m]);
    }
#pragma unroll
    for (int m = 0; m < MF; m++)
        atomicAdd(&g_KV[((size_t)h * MF + m) * DM + tid], acc[m]);

    if (tid < MF) {
        float s = 0.f;
        for (int r = 0; r < rows; r++) s += kpS[r][tid];
        atomicAdd(&g_Ks[h * MF + tid], s);
    }
}

// ---------------------------------------------------------------------------
// Z = (Qp @ KV) / (Qp @ Ksum + 1e-6)    (Qp = QKp, row stride 240)
// ---------------------------------------------------------------------------
__global__ __launch_bounds__(256)
void z_kernel(const float* __restrict__ Qp, float* __restrict__ Z)
{
    __shared__ float qpS[128][31];
    __shared__ float ksS[MF];
    __shared__ float denS[128];

    const int h   = blockIdx.y;
    const int n0  = blockIdx.x * 128;
    const int tid = threadIdx.x;
    const int rows = min(128, NTOT - n0);

    float kv[MF];
#pragma unroll
    for (int m = 0; m < MF; m++)
        kv[m] = g_KV[((size_t)h * MF + m) * DM + tid];
    if (tid < MF) ksS[tid] = g_Ks[h * MF + tid];

    for (int i = tid; i < rows * MF; i += 256) {
        const int r = i / MF, m = i % MF;
        qpS[r][m] = Qp[(size_t)(n0 + r) * NQK + h * MF + m];
    }
    __syncthreads();

    if (tid < rows) {
        float s = 0.f;
#pragma unroll
        for (int m = 0; m < MF; m++) s = fmaf(qpS[tid][m], ksS[m], s);
        denS[tid] = s + 1e-6f;
    }
    __syncthreads();

    for (int r = 0; r < rows; r++) {
        float a = 0.f;
#pragma unroll
        for (int m = 0; m < MF; m++) a = fmaf(qpS[r][m], kv[m], a);
        Z[((size_t)(n0 + r) * HEADS + h) * DM + tid] = a / denS[r];
    }
}

// ---------------------------------------------------------------------------
// Launch
// ---------------------------------------------------------------------------
extern "C" void kernel_launch(void* const* d_in, const int* in_sizes, int n_in,
                              void* d_out, int out_size)
{
    const float* x    = (const float*)d_in[0];
    const float* H    = (const float*)d_in[1];
    const float* proj = (const float*)d_in[2];
    const float* W_in = (const float*)d_in[3];
    const float* b_in = (const float*)d_in[4];
    const float* W_he = (const float*)d_in[5];
    const float* b_he = (const float*)d_in[6];
    const float* ln_g = (const float*)d_in[7];
    const float* ln_b = (const float*)d_in[8];
    const float* Wq   = (const float*)d_in[9];
    const float* bq   = (const float*)d_in[10];
    const float* Wk   = (const float*)d_in[11];
    const float* bk   = (const float*)d_in[12];
    const float* Wv   = (const float*)d_in[13];
    const float* bv   = (const float*)d_in[14];
    const float* Wo   = (const float*)d_in[15];
    const float* bo   = (const float*)d_in[16];

    float* h = (float*)d_out;

    cudaFuncSetAttribute(gemm_tc, cudaFuncAttributeMaxDynamicSharedMemorySize,
                         GEMM_SMEM);

    float *z, *V, *Zb, *QKp, *WT;
    cudaGetSymbolAddress((void**)&z,   g_z);
    cudaGetSymbolAddress((void**)&V,   g_V);
    cudaGetSymbolAddress((void**)&Zb,  g_Zb);
    cudaGetSymbolAddress((void**)&QKp, g_QKp);
    cudaGetSymbolAddress((void**)&WT,  g_WT);

    // weight prep: 2 launches total (keeps ncu -s 5 on a GEMM)
    mega_transpose<<<dim3(32, 32, 8), dim3(32, 8)>>>(W_in, W_he, Wv, Wo, WT);
    mega_fold<<<dim3(NF, 2, LNUM), 256>>>(Wq, bq, Wk, bk, proj, WT);

    const int MB = (NTOT + 127) / 128;
    const dim3 g256(1, MB);      // Nn <= 256: one 256-wide tile
    const dim3 g1024(4, MB);     // Nn = 1024
    const dim3 gHead(MB, HEADS);

    gemm_tc<<<g256, 256, GEMM_SMEM>>>(x, WT + WT_IN, h, b_in, NTOT, 256, 256, 256, 0);
    gemm_tc<<<g256, 256, GEMM_SMEM>>>(H, WT + WT_HE, h, b_he, NTOT, 256, EDIM, 256, 1);

    for (int l = 0; l < LNUM; l++) {
        ln_elu_kernel<<<(NTOT + 7) / 8, 256>>>(h, ln_g + l * DM, ln_b + l * DM, z);

        // [Qp | Kp] = exp(z @ Wqk' + bqk') + 1e-6   (merged, N=240)
        gemm_tc<<<g256, 256, GEMM_SMEM>>>(z, WT + WQK(l), QKp, WT + BQK(l),
                                          NTOT, NQK, 256, NQK, 2);
        // V = z @ Wv + bv
        gemm_tc<<<g1024, 256, GEMM_SMEM>>>(z, WT + WT_V(l), V, bv + (size_t)l * 1024,
                                           NTOT, 1024, 256, 1024, 0);

        zero_kv_kernel<<<(HEADS * MF * DM + 255) / 256, 256>>>();
        kv_kernel<<<gHead, 256>>>(QKp + NF, V);
        z_kernel<<<gHead, 256>>>(QKp, Zb);

        // h += Z @ Wo + bo
        gemm_tc<<<g256, 256, GEMM_SMEM>>>(Zb, WT + WT_O(l), h, bo + (size_t)l * DM,
                                          NTOT, 256, 1024, 256, 1);
    }
}

// round 14
// speedup vs baseline: 2.2155x; 2.2155x over previous
#include <cuda_runtime.h>
#include <math.h>
#include <stdint.h>
#include <mma.h>

using namespace nvcuda;

// Problem constants
#define NTOT 50000
#define EDIM 1000
#define DM   256
#define HEADS 4
#define MF   30
#define LNUM 3
#define NF   (HEADS * MF)          // 120 feature columns
#define NQK  (2 * NF)              // 240: [Qp | Kp] merged

// ---------------------------------------------------------------------------
// Scratch (device globals — no allocations allowed)
// ---------------------------------------------------------------------------
__device__ float g_z  [NTOT * DM];          // ln output
__device__ float g_QKp[NTOT * NQK];         // [Qp | Kp] features
__device__ float g_Qps[NTOT * NF];          // Qp / den
__device__ float g_S  [NF * DM];            // Kp^T @ z
__device__ float g_Ks [NF];                 // sum_n Kp
__device__ float g_KV [NF * DM];            // S @ Wv + Ks (x) bv
__device__ float g_W2t[DM * NF];            // (KV @ Wo)^T  [256 x 120]
// transposed / folded weights
__device__ float g_WT[506576];

#define WT_IN   0
#define WT_HE   65536
#define WQK(l)  (321536 + (l) * 61440)      // 240 rows x 256 (rows 0-119 Q, 120-239 K)
#define BQK(l)  (505856 + (l) * 240)

// ---------------------------------------------------------------------------
// cp.async helpers (base ISA, sm_80+)
// ---------------------------------------------------------------------------
__device__ __forceinline__ uint32_t smem_u32(const void* p) {
    uint32_t a;
    asm("{ .reg .u64 t; cvta.to.shared.u64 t, %1; cvt.u32.u64 %0, t; }"
        : "=r"(a) : "l"(p));
    return a;
}

__device__ __forceinline__ void cpasync16(uint32_t dst, const void* src, int srcsize) {
    asm volatile("cp.async.cg.shared.global [%0], [%1], 16, %2;"
        :: "r"(dst), "l"(src), "r"(srcsize) : "memory");
}
#define CP_COMMIT() asm volatile("cp.async.commit_group;" ::: "memory")
#define CP_WAIT1()  asm volatile("cp.async.wait_group 1;" ::: "memory")

// ---------------------------------------------------------------------------
// WMMA TF32 GEMM: C[M x Nn] = A[M x K] @ Bt^T (+bias) (+C) (or exp epilogue)
//   A  : [M, K]  row-major fp32 (row stride == K)
//   Bt : [Nn, K] row-major fp32 (K-major == wmma col_major B)
//   Block tile 128 x 128, BK = 32, 8 warps (warp tile 64 x 32). K % 4 == 0.
//   mode: 0 = C = v + bias ; 1 = C += v + bias ; 2 = C = exp(v + bias) + 1e-6
// ---------------------------------------------------------------------------
#define BK 32
#define ROWF 36
#define STAGE_F (2 * 128 * ROWF)
#define GEMM_SMEM 73728

__global__ __launch_bounds__(256, 2)
void gemm_tc(const float* __restrict__ A, const float* __restrict__ Bt,
             float* __restrict__ C, const float* __restrict__ bias,
             int M, int Nn, int K, int Cstride, int mode)
{
    extern __shared__ __align__(16) float smem[];

    const int tid  = threadIdx.x;
    const int wid  = tid >> 5;
    const int wm   = wid & 1;          // 0..1 -> 64-row slab
    const int wn   = wid >> 1;         // 0..3 -> 32-col slab
    const int row0 = blockIdx.y * 128;
    const int col0 = blockIdx.x * 128;

    const int T = (K + BK - 1) / BK;

    wmma::fragment<wmma::accumulator, 16, 16, 8, float> acc[4][2];
#pragma unroll
    for (int i = 0; i < 4; i++)
#pragma unroll
        for (int j = 0; j < 2; j++) wmma::fill_fragment(acc[i][j], 0.f);

    auto load_tile = [&](int tt, int ss) {
        float* As = smem + ss * STAGE_F;
        float* Bs = As + 128 * ROWF;
        const uint32_t asb = smem_u32(As);
        const uint32_t bsb = smem_u32(Bs);
        const int kbase = tt * BK;
#pragma unroll
        for (int i = 0; i < 4; i++) {          // A: 1024 16B chunks
            const int id  = tid + i * 256;
            const int row = id >> 3, c = id & 7;
            const int gr = row0 + row;
            const int gk = kbase + c * 4;
            const int ok = (gr < M) && (gk + 4 <= K);
            const float* src = ok ? (A + (size_t)gr * K + gk) : A;
            cpasync16(asb + (row * ROWF + c * 4) * 4, src, ok ? 16 : 0);
        }
#pragma unroll
        for (int i = 0; i < 4; i++) {          // B: 1024 16B chunks
            const int id  = tid + i * 256;
            const int row = id >> 3, c = id & 7;
            const int gn = col0 + row;
            const int gk = kbase + c * 4;
            const int ok = (gn < Nn) && (gk + 4 <= K);
            const float* src = ok ? (Bt + (size_t)gn * K + gk) : Bt;
            cpasync16(bsb + (row * ROWF + c * 4) * 4, src, ok ? 16 : 0);
        }
    };

    load_tile(0, 0);
    CP_COMMIT();

    for (int t = 0; t < T; t++) {
        if (t + 1 < T) load_tile(t + 1, (t + 1) & 1);
        CP_COMMIT();
        CP_WAIT1();
        __syncthreads();

        const float* As = smem + (t & 1) * STAGE_F;
        const float* Bs = As + 128 * ROWF;

#pragma unroll
        for (int ks = 0; ks < 4; ks++) {
            const int k0 = ks * 8;
            wmma::fragment<wmma::matrix_a, 16, 16, 8, wmma::precision::tf32,
                           wmma::row_major> af[4];
            wmma::fragment<wmma::matrix_b, 16, 16, 8, wmma::precision::tf32,
                           wmma::col_major> bf[2];
#pragma unroll
            for (int i = 0; i < 4; i++) {
                wmma::load_matrix_sync(af[i], As + (wm * 64 + i * 16) * ROWF + k0, ROWF);
#pragma unroll
                for (int e = 0; e < af[i].num_elements; e++)
                    af[i].x[e] = wmma::__float_to_tf32(af[i].x[e]);
            }
#pragma unroll
            for (int j = 0; j < 2; j++) {
                wmma::load_matrix_sync(bf[j], Bs + (wn * 32 + j * 16) * ROWF + k0, ROWF);
#pragma unroll
                for (int e = 0; e < bf[j].num_elements; e++)
                    bf[j].x[e] = wmma::__float_to_tf32(bf[j].x[e]);
            }
#pragma unroll
            for (int i = 0; i < 4; i++)
#pragma unroll
                for (int j = 0; j < 2; j++)
                    wmma::mma_sync(acc[i][j], af[i], bf[j], acc[i][j]);
        }
        __syncthreads();
    }

    // epilogue via smem staging (128 x 132)
    float* Cs = smem;
#pragma unroll
    for (int i = 0; i < 4; i++)
#pragma unroll
        for (int j = 0; j < 2; j++)
            wmma::store_matrix_sync(Cs + (wm * 64 + i * 16) * 132 + wn * 32 + j * 16,
                                    acc[i][j], 132, wmma::mem_row_major);
    __syncthreads();

    const int r    = tid >> 1;         // 0..127
    const int half = tid & 1;          // 0..1 -> 64-col half
    const int gr   = row0 + r;
    if (gr < M) {
        const float* sp = Cs + r * 132 + half * 64;
#pragma unroll
        for (int j = 0; j < 16; j++) {
            const int cc = col0 + half * 64 + j * 4;
            if (cc + 4 > Nn) continue;
            float4 v = *(const float4*)(sp + j * 4);
            float4 bv = *(const float4*)(bias + cc);
            v.x += bv.x; v.y += bv.y; v.z += bv.z; v.w += bv.w;
            float* cp = C + (size_t)gr * Cstride + cc;
            if (mode == 1) {
                float4 o = *(float4*)cp;
                v.x += o.x; v.y += o.y; v.z += o.z; v.w += o.w;
            } else if (mode == 2) {
                v.x = __expf(v.x) + 1e-6f; v.y = __expf(v.y) + 1e-6f;
                v.z = __expf(v.z) + 1e-6f; v.w = __expf(v.w) + 1e-6f;
            }
            *(float4*)cp = v;
        }
    }
}

// ---------------------------------------------------------------------------
// Mega-transpose (W_in, W_he only): out[Nn x K] = in[K x Nn]^T
// ---------------------------------------------------------------------------
__global__ void mega_transpose(const float* __restrict__ W_in,
                               const float* __restrict__ W_he,
                               float* __restrict__ WT)
{
    const int z = blockIdx.z;
    const float* src; float* dst; int K, Nn;
    if (z == 0) { src = W_in; dst = WT + WT_IN; K = 256;  Nn = 256; }
    else        { src = W_he; dst = WT + WT_HE; K = EDIM; Nn = 256; }

    const int k0 = blockIdx.x * 32, n0 = blockIdx.y * 32;
    if (k0 >= K || n0 >= Nn) return;

    __shared__ float tile[32][33];
    const int tx = threadIdx.x, ty = threadIdx.y;
#pragma unroll
    for (int r = 0; r < 4; r++) {
        const int k = k0 + ty + r * 8;
        if (k < K && n0 + tx < Nn) tile[ty + r * 8][tx] = src[(size_t)k * Nn + n0 + tx];
    }
    __syncthreads();
#pragma unroll
    for (int r = 0; r < 4; r++) {
        const int n = n0 + ty + r * 8;
        if (n < Nn && k0 + tx < K) dst[(size_t)n * K + k0 + tx] = tile[tx][ty + r * 8];
    }
}

// ---------------------------------------------------------------------------
// Mega-fold: FAVOR+ weight folds, grid (NF, 2, LNUM); y=0 -> Q, y=1 -> K
// ---------------------------------------------------------------------------
__global__ __launch_bounds__(256)
void mega_fold(const float* __restrict__ Wq, const float* __restrict__ bq,
               const float* __restrict__ Wk, const float* __restrict__ bk,
               const float* __restrict__ proj, float* __restrict__ WT)
{
    __shared__ float ps[DM];
    const int l   = blockIdx.z;
    const int isK = blockIdx.y;
    const float* W = (isK ? Wk : Wq) + (size_t)l * DM * HEADS * DM;
    const float* b = (isK ? bk : bq) + (size_t)l * (HEADS * DM);
    float* Wout = WT + WQK(l) + isK * (NF * DM);
    float* bout = WT + BQK(l) + isK * NF;

    const int nn = blockIdx.x;       // 0..119
    const int h = nn / MF, m = nn % MF;
    const int k = threadIdx.x;       // 0..255
    const float c = 0.25f * 0.18257418583505536f;
    ps[k] = c * proj[(size_t)m * DM + k];
    __syncthreads();

    float s = 0.f;
    const float* wp = W + (size_t)k * (HEADS * DM) + h * DM;
#pragma unroll 8
    for (int d = 0; d < DM; d++) s = fmaf(wp[d], ps[d], s);
    Wout[(size_t)nn * DM + k] = s;

    if (k == 0) {
        float sb = 0.f;
        const float* bp = b + h * DM;
        for (int d = 0; d < DM; d++) sb = fmaf(bp[d], ps[d], sb);
        bout[nn] = sb;
    }
}

// ---------------------------------------------------------------------------
// LayerNorm + ELU
// ---------------------------------------------------------------------------
__global__ void ln_elu_kernel(const float* __restrict__ h,
                              const float* __restrict__ gamma,
                              const float* __restrict__ beta,
                              float* __restrict__ z)
{
    const int gw   = blockIdx.x * (blockDim.x >> 5) + (threadIdx.x >> 5);
    const int lane = threadIdx.x & 31;
    if (gw >= NTOT) return;

    const float4* hp = (const float4*)(h + (size_t)gw * DM);
    float4 v0 = hp[lane * 2];
    float4 v1 = hp[lane * 2 + 1];
    float vv[8] = {v0.x, v0.y, v0.z, v0.w, v1.x, v1.y, v1.z, v1.w};

    float s = 0.f;
#pragma unroll
    for (int i = 0; i < 8; i++) s += vv[i];
#pragma unroll
    for (int o = 16; o; o >>= 1) s += __shfl_xor_sync(0xffffffffu, s, o);
    const float mean = s * (1.0f / DM);

    float sq = 0.f;
#pragma unroll
    for (int i = 0; i < 8; i++) { float d = vv[i] - mean; sq = fmaf(d, d, sq); }
#pragma unroll
    for (int o = 16; o; o >>= 1) sq += __shfl_xor_sync(0xffffffffu, sq, o);
    const float inv = rsqrtf(sq * (1.0f / DM) + 1e-5f);

    const int c = lane * 8;
    float out[8];
#pragma unroll
    for (int i = 0; i < 8; i++) {
        float t = (vv[i] - mean) * inv * gamma[c + i] + beta[c + i];
        out[i] = (t > 0.f) ? t : expm1f(t);
    }
    float4* zp = (float4*)(z + (size_t)gw * DM);
    zp[lane * 2]     = make_float4(out[0], out[1], out[2], out[3]);
    zp[lane * 2 + 1] = make_float4(out[4], out[5], out[6], out[7]);
}

// ---------------------------------------------------------------------------
// Zero S / Ksum accumulators
// ---------------------------------------------------------------------------
__global__ void zero_s_kernel()
{
    const int i = blockIdx.x * blockDim.x + threadIdx.x;
    if (i < NF * DM) g_S[i] = 0.f;
    if (i < NF)      g_Ks[i] = 0.f;
}

// ---------------------------------------------------------------------------
// S[hm, k] = sum_n Kp[n, hm] * z[n, k] ; Ksum = sum_n Kp
//   (Kp = QKp + NF, row stride NQK). blockIdx = (n-chunk, head), 256 threads.
// ---------------------------------------------------------------------------
__global__ __launch_bounds__(256)
void s_kernel(const float* __restrict__ Kp, const float* __restrict__ z)
{
    __shared__ float kpS[128][31];
    const int h   = blockIdx.y;
    const int n0  = blockIdx.x * 128;
    const int tid = threadIdx.x;
    const int rows = min(128, NTOT - n0);

    for (int i = tid; i < rows * MF; i += 256) {
        const int r = i / MF, m = i % MF;
        kpS[r][m] = Kp[(size_t)(n0 + r) * NQK + h * MF + m];
    }
    __syncthreads();

    float acc[MF];
#pragma unroll
    for (int m = 0; m < MF; m++) acc[m] = 0.f;

    for (int r = 0; r < rows; r++) {
        const float v = z[(size_t)(n0 + r) * DM + tid];
#pragma unroll
        for (int m = 0; m < MF; m++)
            acc[m] = fmaf(kpS[r][m], v, acc[m]);
    }
#pragma unroll
    for (int m = 0; m < MF; m++)
        atomicAdd(&g_S[(size_t)(h * MF + m) * DM + tid], acc[m]);

    if (tid < MF) {
        float s = 0.f;
        for (int r = 0; r < rows; r++) s += kpS[r][tid];
        atomicAdd(&g_Ks[h * MF + tid], s);
    }
}

// ---------------------------------------------------------------------------
// KV[hm, d] = sum_k S[hm, k] * Wv[k, h*256+d] + Ks[hm] * bv[h*256+d]
//   grid = NF blocks, 256 threads (d)
// ---------------------------------------------------------------------------
__global__ __launch_bounds__(256)
void kv2_kernel(const float* __restrict__ Wv, const float* __restrict__ bv)
{
    __shared__ float srow[DM];
    const int hm = blockIdx.x;       // 0..119
    const int h  = hm / MF;
    const int d  = threadIdx.x;      // 0..255
    srow[d] = g_S[(size_t)hm * DM + d];
    __syncthreads();

    float acc = 0.f;
    const float* wp = Wv + h * DM + d;
#pragma unroll 8
    for (int k = 0; k < DM; k++)
        acc = fmaf(srow[k], wp[(size_t)k * (HEADS * DM)], acc);
    g_KV[(size_t)hm * DM + d] = acc + g_Ks[hm] * bv[h * DM + d];
}

// ---------------------------------------------------------------------------
// W2t[j, hm] = sum_d KV[hm, d] * Wo[h*256+d, j]
//   grid = NF blocks, 256 threads (j). Output K-major [256 x 120] for gemm_tc.
// ---------------------------------------------------------------------------
__global__ __launch_bounds__(256)
void w2_kernel(const float* __restrict__ Wo)
{
    __shared__ float kvrow[DM];
    const int hm = blockIdx.x;       // 0..119
    const int h  = hm / MF;
    const int j  = threadIdx.x;      // 0..255
    kvrow[j] = g_KV[(size_t)hm * DM + j];
    __syncthreads();

    float acc = 0.f;
    const float* wp = Wo + (size_t)(h * DM) * DM + j;
#pragma unroll 8
    for (int d = 0; d < DM; d++)
        acc = fmaf(kvrow[d], wp[(size_t)d * DM], acc);
    g_W2t[(size_t)j * NF + hm] = acc;
}

// ---------------------------------------------------------------------------
// Qps[n, hm] = Qp[n, hm] / (sum_m Qp[n, h*MF+m] * Ks[h*MF+m] + 1e-6)
//   one thread per row n
// ---------------------------------------------------------------------------
__global__ __launch_bounds__(256)
void qps_kernel(const float* __restrict__ QKp, float* __restrict__ Qps)
{
    __shared__ float ks[NF];
    const int tid = threadIdx.x;
    if (tid < NF) ks[tid] = g_Ks[tid];
    __syncthreads();

    const int n = blockIdx.x * 256 + tid;
    if (n >= NTOT) return;
    const float* q = QKp + (size_t)n * NQK;
    float* o = Qps + (size_t)n * NF;

#pragma unroll
    for (int h = 0; h < HEADS; h++) {
        float den = 0.f;
#pragma unroll
        for (int m = 0; m < MF; m++)
            den = fmaf(q[h * MF + m], ks[h * MF + m], den);
        const float inv = 1.0f / (den + 1e-6f);
#pragma unroll
        for (int m = 0; m < MF; m++)
            o[h * MF + m] = q[h * MF + m] * inv;
    }
}

// ---------------------------------------------------------------------------
// Launch
// ---------------------------------------------------------------------------
extern "C" void kernel_launch(void* const* d_in, const int* in_sizes, int n_in,
                              void* d_out, int out_size)
{
    const float* x    = (const float*)d_in[0];
    const float* H    = (const float*)d_in[1];
    const float* proj = (const float*)d_in[2];
    const float* W_in = (const float*)d_in[3];
    const float* b_in = (const float*)d_in[4];
    const float* W_he = (const float*)d_in[5];
    const float* b_he = (const float*)d_in[6];
    const float* ln_g = (const float*)d_in[7];
    const float* ln_b = (const float*)d_in[8];
    const float* Wq   = (const float*)d_in[9];
    const float* bq   = (const float*)d_in[10];
    const float* Wk   = (const float*)d_in[11];
    const float* bk   = (const float*)d_in[12];
    const float* Wv   = (const float*)d_in[13];
    const float* bv   = (const float*)d_in[14];
    const float* Wo   = (const float*)d_in[15];
    const float* bo   = (const float*)d_in[16];

    float* h = (float*)d_out;

    cudaFuncSetAttribute(gemm_tc, cudaFuncAttributeMaxDynamicSharedMemorySize,
                         GEMM_SMEM);

    float *z, *QKp, *Qps, *W2t, *WT;
    cudaGetSymbolAddress((void**)&z,   g_z);
    cudaGetSymbolAddress((void**)&QKp, g_QKp);
    cudaGetSymbolAddress((void**)&Qps, g_Qps);
    cudaGetSymbolAddress((void**)&W2t, g_W2t);
    cudaGetSymbolAddress((void**)&WT,  g_WT);

    // weight prep: 2 launches
    mega_transpose<<<dim3(32, 8, 2), dim3(32, 8)>>>(W_in, W_he, WT);
    mega_fold<<<dim3(NF, 2, LNUM), 256>>>(Wq, bq, Wk, bk, proj, WT);

    const int MB = (NTOT + 127) / 128;
    const dim3 g256(2, MB);      // Nn = 256
    const dim3 g240(2, MB);      // Nn = 240
    const dim3 gHead(MB, HEADS);

    // h = x @ W_in + b_in ; h += H @ W_he + b_he
    gemm_tc<<<g256, 256, GEMM_SMEM>>>(x, WT + WT_IN, h, b_in, NTOT, 256, 256, 256, 0);
    gemm_tc<<<g256, 256, GEMM_SMEM>>>(H, WT + WT_HE, h, b_he, NTOT, 256, EDIM, 256, 1);

    for (int l = 0; l < LNUM; l++) {
        ln_elu_kernel<<<(NTOT + 7) / 8, 256>>>(h, ln_g + l * DM, ln_b + l * DM, z);

        // [Qp | Kp] = exp(z @ Wqk' + bqk') + 1e-6   (merged, N=240)
        gemm_tc<<<g240, 256, GEMM_SMEM>>>(z, WT + WQK(l), QKp, WT + BQK(l),
                                          NTOT, NQK, 256, NQK, 2);

        // S = Kp^T @ z ; Ksum = sum Kp
        zero_s_kernel<<<(NF * DM + 255) / 256, 256>>>();
        s_kernel<<<gHead, 256>>>(QKp + NF, z);

        // KV = S @ Wv + Ks (x) bv ;  W2t = (KV @ Wo)^T
        kv2_kernel<<<NF, 256>>>(Wv + (size_t)l * DM * HEADS * DM,
                                bv + (size_t)l * (HEADS * DM));
        w2_kernel<<<NF, 256>>>(Wo + (size_t)l * (HEADS * DM) * DM);

        // Qps = Qp / (Qp . Ksum + 1e-6)
        qps_kernel<<<(NTOT + 255) / 256, 256>>>(QKp, Qps);

        // h += Qps @ W2t^T + bo    (M=50000, N=256, K=120)
        gemm_tc<<<g256, 256, GEMM_SMEM>>>(Qps, W2t, h, bo + (size_t)l * DM,
                                          NTOT, 256, NF, 256, 1);
    }
}